// round 10
// baseline (speedup 1.0000x reference)
#include <cuda_runtime.h>
#include <cstdint>

// Fixed problem shapes: E<=4096, IN=OUT=256, N_NODES=1024
#define MAX_E 4096
#define NN    1024
#define FC    256
#define FC4   64
#define NB    128          // blocks in K1/K2
#define NT    256
#define NPB   (NN / NB)    // 8 nodes per block
#define EPB   (MAX_E / NB) // 32 edges per block (w-output slice)
#define LCAP  2048         // smem incidence-list capacity per block

// ---------------- global scratch (fully rewritten every run) --------------
__device__ float g_w[MAX_E];
__device__ float g_t[NN * FC];
__device__ float g_T[NN * FC];

// ============ K1: block-local hist + incidence -> t rows + w slice =========
__global__ __launch_bounds__(NT)
void k_build_t(const float* __restrict__ x, const int* __restrict__ ei,
               const unsigned char* __restrict__ bb, int E) {
    const int tid = threadIdx.x;
    const int b   = blockIdx.x;
    const int n0  = b * NPB;

    __shared__ int s_hist[NN];     // hs low 16 bits, hd high 16 bits
    __shared__ int s_sl[NN];       // self-loop count
    __shared__ int s_list[LCAP];   // e | nl<<16 | srcflag<<19
    __shared__ int s_cnt;
    __shared__ int s_flags;        // bit0: any nonzero byte, bit1: misaligned nonzero

    for (int i = tid; i < NN; i += NT) { s_hist[i] = 0; s_sl[i] = 0; }
    if (tid == 0) { s_cnt = 0; s_flags = 0; }
    __syncthreads();

    {
        int fl = 0;
        for (int e = tid; e < E; e += NT) {
            int s = ei[e], d = ei[E + e];
            atomicAdd(&s_hist[s], 1);
            atomicAdd(&s_hist[d], 0x10000);
            if (s == d) atomicAdd(&s_sl[s], 1);
            unsigned char v = bb[e];
            if (v) { fl |= 1; if (e & 3) fl |= 2; }
            unsigned su = (unsigned)(s - n0), du = (unsigned)(d - n0);
            if (su < NPB) {
                int p = atomicAdd(&s_cnt, 1);
                if (p < LCAP) s_list[p] = e | ((int)su << 16) | (1 << 19);
            }
            if (du < NPB) {
                int p = atomicAdd(&s_cnt, 1);
                if (p < LCAP) s_list[p] = e | ((int)du << 16);
            }
        }
        if (fl) atomicOr(&s_flags, fl);
    }
    __syncthreads();

    const int flags = s_flags;
    const int cnt   = min(s_cnt, LCAP);

    // write w for this block's edge slice [b*EPB, (b+1)*EPB)
    if (tid < EPB) {
        int e = b * EPB + tid;
        if (e < E) {
            int s = ei[e], d = ei[E + e];
            float w = 0.0f;
            if (s != d) {
                int hs = s_hist[s], hd = s_hist[d];
                int deg = (hs & 0xffff) + (hs >> 16)
                        + (hd & 0xffff) + (hd >> 16)
                        - 2 * (s_sl[s] + s_sl[d]);
                int dir;
                if (flags & 2)      dir = bb[e] != 0;            // byte layout
                else if (flags & 1) dir = ((const int*)bb)[e] != 0; // int layout
                else                dir = 0;                     // all false
                w = (dir ? -1.0f : 1.0f) * rsqrtf((float)deg);
            }
            g_w[e] = w;
        }
    }

    // t rows for this block's 8 nodes: 4 nodes at a time (64 threads each)
    {
        const int sub = tid >> 6;      // 0..3
        const int c4  = tid & 63;
        #pragma unroll
        for (int r = 0; r < NPB / 4; r++) {
            const int nl = r * 4 + sub;          // local node 0..7
            float4 acc = make_float4(0.f, 0.f, 0.f, 0.f);
            for (int j = 0; j < cnt; j++) {
                int ent = s_list[j];
                if (((ent >> 16) & 7) != nl) continue;
                int e = ent & 0xffff;
                if (e >= E) continue;
                int s = ei[e], d = ei[E + e];
                if (s == d) continue;
                int hs = s_hist[s], hd = s_hist[d];
                int deg = (hs & 0xffff) + (hs >> 16)
                        + (hd & 0xffff) + (hd >> 16)
                        - 2 * (s_sl[s] + s_sl[d]);
                int dir;
                if (flags & 2)      dir = bb[e] != 0;
                else if (flags & 1) dir = ((const int*)bb)[e] != 0;
                else                dir = 0;
                float w = (dir ? -1.0f : 1.0f) * rsqrtf((float)deg);
                if (ent & (1 << 19)) w = -w;     // src side contributes negatively
                float4 v = ((const float4*)x)[e * FC4 + c4];
                acc.x = fmaf(w, v.x, acc.x);
                acc.y = fmaf(w, v.y, acc.y);
                acc.z = fmaf(w, v.z, acc.z);
                acc.w = fmaf(w, v.w, acc.w);
            }
            ((float4*)g_t)[(n0 + nl) * FC4 + c4] = acc;
        }
    }
}

// ============ K2: GEMM  T = t @ W^T  (M=1024, N=256, K=256) ================
__global__ __launch_bounds__(NT)
void k_gemm(const float* __restrict__ W) {
    __shared__ float As[16][33];
    __shared__ float Bs[16][65];
    const int tid = threadIdx.x;
    const int b   = blockIdx.x;
    int gx = b & 3, gy = b >> 2;
    int m0 = gy * 32, n0 = gx * 64;
    int tx = tid & 15, ty = tid >> 4;

    float acc[2][4];
    #pragma unroll
    for (int i = 0; i < 2; i++)
        #pragma unroll
        for (int j = 0; j < 4; j++) acc[i][j] = 0.0f;

    for (int k0 = 0; k0 < FC; k0 += 16) {
        if (tid < 128) {                   // A tile 32x16
            int row = tid >> 2, kq = (tid & 3) << 2;
            float4 v = *(const float4*)&g_t[(m0 + row) * FC + k0 + kq];
            As[kq + 0][row] = v.x; As[kq + 1][row] = v.y;
            As[kq + 2][row] = v.z; As[kq + 3][row] = v.w;
        }
        {                                  // B tile 64x16
            int n = tid >> 2, kq = (tid & 3) << 2;
            float4 v = *(const float4*)&W[(n0 + n) * FC + k0 + kq];
            Bs[kq + 0][n] = v.x; Bs[kq + 1][n] = v.y;
            Bs[kq + 2][n] = v.z; Bs[kq + 3][n] = v.w;
        }
        __syncthreads();
        #pragma unroll
        for (int k = 0; k < 16; k++) {
            float a0 = As[k][ty * 2 + 0];
            float a1 = As[k][ty * 2 + 1];
            float w4[4];
            #pragma unroll
            for (int j = 0; j < 4; j++) w4[j] = Bs[k][tx * 4 + j];
            #pragma unroll
            for (int j = 0; j < 4; j++) {
                acc[0][j] = fmaf(a0, w4[j], acc[0][j]);
                acc[1][j] = fmaf(a1, w4[j], acc[1][j]);
            }
        }
        __syncthreads();
    }
    #pragma unroll
    for (int i = 0; i < 2; i++) {
        float4 v = make_float4(acc[i][0], acc[i][1], acc[i][2], acc[i][3]);
        *(float4*)&g_T[(m0 + ty * 2 + i) * FC + n0 + tx * 4] = v;
    }
}

// ============ K3: y_e = w_e * (T[dst_e] - T[src_e]) ========================
__global__ __launch_bounds__(NT)
void k_y(const int* __restrict__ ei, float* __restrict__ y, int E) {
    int i = blockIdx.x * NT + threadIdx.x;
    if (i >= E * FC4) return;
    int e = i >> 6, c4 = i & 63;
    float w = g_w[e];
    int s = ei[e], d = ei[E + e];
    float4 vd = ((const float4*)g_T)[d * FC4 + c4];
    float4 vs = ((const float4*)g_T)[s * FC4 + c4];
    float4 o;
    o.x = w * (vd.x - vs.x); o.y = w * (vd.y - vs.y);
    o.z = w * (vd.z - vs.z); o.w = w * (vd.w - vs.w);
    ((float4*)y)[i] = o;
}

// ---------------- launch ---------------------------------------------------
extern "C" void kernel_launch(void* const* d_in, const int* in_sizes, int n_in,
                              void* d_out, int out_size) {
    const float* x     = (const float*)d_in[0];   // [E, 256]
    const float* W     = (const float*)d_in[1];   // [256, 256]
    const int*   ei    = (const int*)d_in[2];     // [2, E]
    const void*  isdir = d_in[3];                 // [E] bool or int32

    int E = in_sizes[2] / 2;
    float* y = (float*)d_out;

    k_build_t<<<NB, NT>>>(x, ei, (const unsigned char*)isdir, E);
    k_gemm<<<NB, NT>>>(W);
    k_y<<<(E * FC4 + NT - 1) / NT, NT>>>(ei, y, E);
}